// round 15
// baseline (speedup 1.0000x reference)
#include <cuda_runtime.h>
#include <stdint.h>
#include <math.h>

#define NIMG   16
#define NANCH  8732
#define NCLS   80
#define NCLS1  81
#define KCAND  400
#define KOUT   200
#define CAP    16384
#define CLIPV  4.135166556742356f

__device__ float g_cls[NIMG * NANCH * NCLS1];
__device__ float g_reg[NIMG * NANCH * 4];
__device__ float g_scr[NIMG * NANCH * NCLS];
__device__ unsigned int g_hist[NIMG * 65536];
__device__ unsigned int g_thr[NIMG];
__device__ int g_cnt[NIMG];
__device__ unsigned long long g_cand[NIMG * CAP];
__device__ float g_cbox[NIMG * KCAND * 4];
__device__ float g_cscore[NIMG * KCAND];
__device__ int g_ccls[NIMG * KCAND];
__device__ int g_ckeep[NIMG * KCAND];

// f32x2 helpers
#define FMA2(acc, a, b) asm("fma.rn.f32x2 %0, %1, %2, %0;" : "+l"(acc) : "l"(a), "l"(b))
#define PACK2(out, lo, hi) asm("mov.b64 %0, {%1, %2};" : "=l"(out) : "r"(lo), "r"(hi))
#define UNPACK2(lo, hi, in) asm("mov.b64 {%0, %1}, %2;" : "=r"(lo), "=r"(hi) : "l"(in))

// zero hist in 3 parts so conv_all is visible launch #4 (ncu -s 5 window)
#define ZPART 349526
__global__ void zero_kernel(int part) {
    int i = part * ZPART + blockIdx.x * blockDim.x + threadIdx.x;
    if (i < NIMG * 65536 && i < (part + 1) * ZPART) g_hist[i] = 0u;
    if (part == 0 && blockIdx.x == 0 && threadIdx.x < NIMG) g_cnt[threadIdx.x] = 0;
}

// ---------------- one fused conv for all 12 heads (128-thread CTAs) ----------------
struct AllDesc {
    const float* x[12];
    const float* w[12];
    const float* bs[12];
    int C[12], H[12], OC[12], base[12], an[12], cta0[12], gx[12], tl[12];
};

__global__ __launch_bounds__(128) void conv_all(AllDesc D, float* __restrict__ outc,
                                                float* __restrict__ outr)
{
    __shared__ float As[2][16][128];   // [buf][k][m]
    __shared__ float Bs[2][16][64];    // [buf][k][n]

    int bid = blockIdx.x, s = 0;
#pragma unroll
    for (int i = 1; i < 12; i++) if (bid >= D.cta0[i]) s = i;
    int local = bid - D.cta0[s];
    const int C = D.C[s], H = D.H[s], W = H, OC = D.OC[s], an = D.an[s], base = D.base[s];
    const float* x = D.x[s];
    const float* w = D.w[s];
    const float* bias = D.bs[s];
    const int HW = H * W, N = NIMG * HW, K = C * 9, NCH = K >> 4;
    const int tid = threadIdx.x;

    if (D.tl[s] == NCLS1) {
        // ======== cls path: 128(M)x64(N) tile, 8x8 microtile, FFMA2, pipelined ========
        int gx = D.gx[s];
        int bx = local % gx, by = local / gx;
        const int m0 = by * 128, n0 = bx * 64;
        // B fill: thread owns pixel bn (0..63), 8 k's at bkb
        const int bn = tid & 63, bkb = (tid >> 6) * 8;
        const int n = n0 + bn;
        const bool nv = (n < N);
        int bimg = 0, py = 0, px = 0;
        if (nv) { bimg = n / HW; int rem = n - bimg * HW; py = rem / W; px = rem - py * W; }
        const float* xb = x + (size_t)bimg * C * HW;
        // A fill: thread owns weight row am=tid (0..127), 16 k's
        const int am = tid;
        const bool mv = (m0 + am) < OC;
        const float* wp = w + (size_t)(mv ? (m0 + am) : 0) * K;
        const int tx = tid & 7, ty = tid >> 3;

        unsigned long long ch2[32];
        float ms[64], cp[64], pa[16], pb[8];
#pragma unroll
        for (int j = 0; j < 32; j++) ch2[j] = 0ULL;
#pragma unroll
        for (int j = 0; j < 64; j++) { ms[j] = 0.f; cp[j] = 0.f; }

        auto ldg = [&](int c) {
            int k0 = c << 4;
            if (mv) {
#pragma unroll
                for (int q = 0; q < 4; q++) {
                    float4 a = *(const float4*)(wp + k0 + q * 4);
                    pa[q * 4 + 0] = a.x; pa[q * 4 + 1] = a.y;
                    pa[q * 4 + 2] = a.z; pa[q * 4 + 3] = a.w;
                }
            } else {
#pragma unroll
                for (int i = 0; i < 16; i++) pa[i] = 0.f;
            }
#pragma unroll
            for (int i = 0; i < 8; i++) {
                int k = k0 + bkb + i;
                int ic = k / 9, r = k - ic * 9, ky = r / 3, kx = r - ky * 3;
                int iy = py + ky - 1, ix = px + kx - 1;
                float v = 0.f;
                if (nv && (unsigned)iy < (unsigned)H && (unsigned)ix < (unsigned)W)
                    v = xb[(ic * H + iy) * W + ix];
                pb[i] = v;
            }
        };
        auto st = [&](int bb) {
#pragma unroll
            for (int i = 0; i < 16; i++) As[bb][i][am] = pa[i];
#pragma unroll
            for (int i = 0; i < 8; i++) Bs[bb][bkb + i][bn] = pb[i];
        };

        ldg(0); st(0); __syncthreads();

        for (int c = 0; c < NCH; c++) {
            const int b = c & 1;
            if (c + 1 < NCH) ldg(c + 1);
#pragma unroll
            for (int kk = 0; kk < 16; kk++) {
                ulonglong2 Ap0 = *(const ulonglong2*)&As[b][kk][ty * 8];
                ulonglong2 Ap1 = *(const ulonglong2*)&As[b][kk][ty * 8 + 4];
                unsigned long long a2[4] = {Ap0.x, Ap0.y, Ap1.x, Ap1.y};
                float4 B0 = *(const float4*)&Bs[b][kk][tx * 8];
                float4 B1 = *(const float4*)&Bs[b][kk][tx * 8 + 4];
                float bv[8] = {B0.x, B0.y, B0.z, B0.w, B1.x, B1.y, B1.z, B1.w};
                unsigned long long b2[8];
#pragma unroll
                for (int j = 0; j < 8; j++) {
                    unsigned br = __float_as_uint(bv[j]);
                    PACK2(b2[j], br, br);
                }
#pragma unroll
                for (int i2 = 0; i2 < 4; i2++)
#pragma unroll
                    for (int j = 0; j < 8; j++)
                        FMA2(ch2[i2 * 8 + j], a2[i2], b2[j]);
            }
            if ((c & 3) == 3) {   // Kahan merge every 64 k (NCH % 4 == 0 for all heads)
#pragma unroll
                for (int i2 = 0; i2 < 4; i2++)
#pragma unroll
                    for (int j = 0; j < 8; j++) {
                        unsigned rlo, rhi;
                        UNPACK2(rlo, rhi, ch2[i2 * 8 + j]);
                        int e0 = (2 * i2) * 8 + j, e1 = (2 * i2 + 1) * 8 + j;
                        float v0 = __uint_as_float(rlo), v1 = __uint_as_float(rhi);
                        float y0 = __fsub_rn(v0, cp[e0]);
                        float t0 = __fadd_rn(ms[e0], y0);
                        cp[e0] = __fsub_rn(__fsub_rn(t0, ms[e0]), y0);
                        ms[e0] = t0;
                        float y1 = __fsub_rn(v1, cp[e1]);
                        float t1 = __fadd_rn(ms[e1], y1);
                        cp[e1] = __fsub_rn(__fsub_rn(t1, ms[e1]), y1);
                        ms[e1] = t1;
                        ch2[i2 * 8 + j] = 0ULL;
                    }
            }
            if (c + 1 < NCH) { st(b ^ 1); __syncthreads(); }
        }

#pragma unroll
        for (int i = 0; i < 8; i++) {
            int m = m0 + ty * 8 + i;
            if (m >= OC) continue;
            float bv = bias[m];
            int a_idx = m / NCLS1, t = m - a_idx * NCLS1;
#pragma unroll
            for (int j = 0; j < 8; j++) {
                int nn = n0 + tx * 8 + j;
                if (nn >= N) continue;
                int bi = nn / HW, rem = nn - bi * HW;
                int anchor = base + rem * an + a_idx;
                outc[((size_t)bi * NANCH + anchor) * NCLS1 + t] =
                    __fadd_rn(__fadd_rn(ms[i * 8 + j], cp[i * 8 + j]), bv);
            }
        }
    } else {
        // ======== reg path: 128 pixels/CTA, thread owns a column of 24 oc ========
        const int n = local * 128 + tid;
        const bool nv = (n < N);
        int bimg = 0, py = 0, px = 0;
        if (nv) { bimg = n / HW; int rem = n - bimg * HW; py = rem / W; px = rem - py * W; }
        const float* xb = x + (size_t)bimg * C * HW;
        float* Asr = &As[0][0][0];   // 16 x 24 chunk of weights

        float acc[24], cpp[24], chh[24];
#pragma unroll
        for (int m = 0; m < 24; m++) { acc[m] = 0.f; cpp[m] = 0.f; chh[m] = 0.f; }

        for (int c = 0; c < NCH; c++) {
            int k0 = c << 4;
            float bvv[16];
#pragma unroll
            for (int i = 0; i < 16; i++) {
                int k = k0 + i;
                int ic = k / 9, r = k - ic * 9, ky = r / 3, kx = r - ky * 3;
                int iy = py + ky - 1, ix = px + kx - 1;
                float v = 0.f;
                if (nv && (unsigned)iy < (unsigned)H && (unsigned)ix < (unsigned)W)
                    v = xb[(ic * H + iy) * W + ix];
                bvv[i] = v;
            }
            for (int f = tid; f < 384; f += 128) {
                int k = f / 24, m = f - k * 24;
                Asr[k * 24 + m] = (m < OC) ? w[(size_t)m * K + k0 + k] : 0.f;
            }
            __syncthreads();
#pragma unroll
            for (int kk = 0; kk < 16; kk++) {
                float b = bvv[kk];
#pragma unroll
                for (int m = 0; m < 24; m++)
                    chh[m] += Asr[kk * 24 + m] * b;
            }
            __syncthreads();
            if (c & 1) {
#pragma unroll
                for (int m = 0; m < 24; m++) {
                    float y = __fsub_rn(chh[m], cpp[m]);
                    float t = __fadd_rn(acc[m], y);
                    cpp[m] = __fsub_rn(__fsub_rn(t, acc[m]), y);
                    acc[m] = t;
                    chh[m] = 0.f;
                }
            }
        }
        if (nv) {
            int bi = n / HW, rem = n - bi * HW;
            for (int m = 0; m < OC; m++) {
                int a_idx = m >> 2, t = m & 3;
                int anchor = base + rem * an + a_idx;
                outr[((size_t)bi * NANCH + anchor) * 4 + t] =
                    __fadd_rn(__fadd_rn(acc[m], cpp[m]), bias[m]);
            }
        }
    }
}

__global__ void softmax_kernel() {
    int gw = (blockIdx.x * blockDim.x + threadIdx.x) >> 5;
    int lane = threadIdx.x & 31;
    if (gw >= NIMG * NANCH) return;
    const float* row = g_cls + (size_t)gw * NCLS1;
    float x0 = row[lane], x1 = row[lane + 32];
    float x2 = (lane < 17) ? row[lane + 64] : -3.4e38f;
    float m = fmaxf(x0, fmaxf(x1, x2));
    for (int o = 16; o; o >>= 1) m = fmaxf(m, __shfl_xor_sync(0xffffffffu, m, o));
    float e0 = expf(x0 - m), e1 = expf(x1 - m);
    float e2 = (lane < 17) ? expf(x2 - m) : 0.f;
    float s = e0 + e1 + e2;
    for (int o = 16; o; o >>= 1) s += __shfl_xor_sync(0xffffffffu, s, o);
    float* outp = g_scr + (size_t)gw * NCLS;
    if (lane >= 1) { float p = e0 / s; outp[lane - 1]  = (p > 0.01f) ? p : 0.f; }
    {               float p = e1 / s; outp[lane + 31] = (p > 0.01f) ? p : 0.f; }
    if (lane < 17) { float p = e2 / s; outp[lane + 63] = (p > 0.01f) ? p : 0.f; }
}

__global__ void hist_kernel() {
    int i = blockIdx.x * blockDim.x + threadIdx.x;
    if (i >= NIMG * NANCH * NCLS) return;
    unsigned b = __float_as_uint(g_scr[i]);
    if (b) {
        int img = i / (NANCH * NCLS);
        atomicAdd(&g_hist[img * 65536 + (b >> 16)], 1u);
    }
}

__global__ void select_kernel() {
    __shared__ unsigned csum[256];
    int img = blockIdx.x, tid = threadIdx.x;
    const unsigned* h = g_hist + img * 65536;
    unsigned s = 0;
    for (int j = 0; j < 256; j++) s += h[tid * 256 + j];
    csum[tid] = s;
    __syncthreads();
    if (tid == 0) {
        unsigned cum = 0; int c;
        for (c = 255; c >= 0; c--) {
            if (cum + csum[c] >= KCAND) break;
            cum += csum[c];
        }
        unsigned T = 1u;
        if (c >= 0) {
            int b;
            for (b = c * 256 + 255; b >= c * 256; b--) {
                cum += h[b];
                if (cum >= KCAND) break;
            }
            if (b < c * 256) b = c * 256;
            T = ((unsigned)b) << 16;
            if (T == 0u) T = 1u;
        }
        g_thr[img] = T;
    }
}

__global__ void compact_kernel() {
    int i = blockIdx.x * blockDim.x + threadIdx.x;
    if (i >= NIMG * NANCH * NCLS) return;
    unsigned b = __float_as_uint(g_scr[i]);
    int img = i / (NANCH * NCLS);
    if (b >= g_thr[img]) {
        int p = atomicAdd(&g_cnt[img], 1);
        if (p < CAP) {
            unsigned fidx = (unsigned)(i - img * NANCH * NCLS);
            g_cand[img * CAP + p] =
                ((unsigned long long)b << 32) | (unsigned long long)(0xFFFFFFFFu - fidx);
        }
    }
}

__global__ void sort_decode_kernel(const float* __restrict__ priors) {
    extern __shared__ unsigned long long sk[];
    int img = blockIdx.x, tid = threadIdx.x, nt = blockDim.x;
    int cnt = g_cnt[img];
    if (cnt > CAP) cnt = CAP;
    for (int i = tid; i < CAP; i += nt)
        sk[i] = (i < cnt) ? g_cand[img * CAP + i] : 0ULL;
    __syncthreads();
    for (int k = 2; k <= CAP; k <<= 1) {
        for (int j = k >> 1; j > 0; j >>= 1) {
            for (int i = tid; i < CAP; i += nt) {
                int ixj = i ^ j;
                if (ixj > i) {
                    unsigned long long a = sk[i], b = sk[ixj];
                    bool desc = ((i & k) == 0);
                    if (desc ? (a < b) : (a > b)) { sk[i] = b; sk[ixj] = a; }
                }
            }
            __syncthreads();
        }
    }
    for (int r = tid; r < KCAND; r += nt) {
        unsigned long long key = sk[r];
        unsigned bits = (unsigned)(key >> 32);
        unsigned fidx = 0xFFFFFFFFu - (unsigned)(key & 0xFFFFFFFFull);
        float s = __uint_as_float(bits);
        if (bits == 0u) { s = 0.f; fidx = 0u; }
        int anc = (int)(fidx / NCLS);
        int cls = (int)(fidx - (unsigned)anc * NCLS) + 1;
        const float* d  = g_reg + ((size_t)img * NANCH + anc) * 4;
        const float* pr = priors + (size_t)anc * 4;
        float cx = __fadd_rn(pr[0], __fmul_rn(__fmul_rn(d[0], 0.1f), pr[2]));
        float cy = __fadd_rn(pr[1], __fmul_rn(__fmul_rn(d[1], 0.1f), pr[3]));
        float w  = __fmul_rn(pr[2], expf(fminf(__fmul_rn(d[2], 0.2f), CLIPV)));
        float h  = __fmul_rn(pr[3], expf(fminf(__fmul_rn(d[3], 0.2f), CLIPV)));
        float hw = __fmul_rn(0.5f, w), hh = __fmul_rn(0.5f, h);
        float x1 = fminf(fmaxf(__fsub_rn(cx, hw), 0.f), 300.f);
        float y1 = fminf(fmaxf(__fsub_rn(cy, hh), 0.f), 300.f);
        float x2 = fminf(fmaxf(__fadd_rn(cx, hw), 0.f), 300.f);
        float y2 = fminf(fmaxf(__fadd_rn(cy, hh), 0.f), 300.f);
        bool valid = (s > 0.f) && (x2 > x1) && (y2 > y1);
        int o = img * KCAND + r;
        g_cbox[o * 4 + 0] = x1; g_cbox[o * 4 + 1] = y1;
        g_cbox[o * 4 + 2] = x2; g_cbox[o * 4 + 3] = y2;
        g_cscore[o] = valid ? s : 0.f;
        g_ccls[o] = cls;
        g_ckeep[o] = valid ? 1 : 0;
    }
}

__global__ void nms_kernel() {
    __shared__ float bx1[KCAND], by1[KCAND], bx2[KCAND], by2[KCAND], ar[KCAND];
    __shared__ int kc[KCAND], kp[KCAND];
    int img = blockIdx.x, tid = threadIdx.x, nt = blockDim.x;
    for (int i = tid; i < KCAND; i += nt) {
        int o = img * KCAND + i;
        int c = g_ccls[o];
        float off = __fmul_rn((float)c, 301.0f);
        float a1 = __fadd_rn(g_cbox[o * 4 + 0], off);
        float a2 = __fadd_rn(g_cbox[o * 4 + 1], off);
        float a3 = __fadd_rn(g_cbox[o * 4 + 2], off);
        float a4 = __fadd_rn(g_cbox[o * 4 + 3], off);
        bx1[i] = a1; by1[i] = a2; bx2[i] = a3; by2[i] = a4;
        ar[i] = __fmul_rn(__fsub_rn(a3, a1), __fsub_rn(a4, a2));
        kc[i] = c;
        kp[i] = g_ckeep[o];
    }
    for (int i = 0; i < KCAND; i++) {
        __syncthreads();
        if (!kp[i]) continue;
        float ix1 = bx1[i], iy1 = by1[i], ix2 = bx2[i], iy2 = by2[i], ia = ar[i];
        int ic = kc[i];
        for (int j = i + 1 + tid; j < KCAND; j += nt) {
            if (kp[j] && kc[j] == ic) {
                float w = fmaxf(__fsub_rn(fminf(ix2, bx2[j]), fmaxf(ix1, bx1[j])), 0.f);
                float h = fmaxf(__fsub_rn(fminf(iy2, by2[j]), fmaxf(iy1, by1[j])), 0.f);
                float inter = __fmul_rn(w, h);
                float denom = __fadd_rn(__fsub_rn(__fadd_rn(ia, ar[j]), inter), 1e-9f);
                if (__fdiv_rn(inter, denom) > 0.45f) kp[j] = 0;
            }
        }
    }
    __syncthreads();
    for (int i = tid; i < KCAND; i += nt) g_ckeep[img * KCAND + i] = kp[i];
}

__global__ void final_kernel(float* __restrict__ out) {
    __shared__ unsigned long long key[512];
    int img = blockIdx.x, tid = threadIdx.x;
    if (tid < KCAND) {
        int o = img * KCAND + tid;
        float ms = g_ckeep[o] ? g_cscore[o] : 0.f;
        key[tid] = ((unsigned long long)__float_as_uint(ms) << 32) |
                   (unsigned long long)(0xFFFFFFFFu - (unsigned)tid);
    } else key[tid] = 0ULL;
    __syncthreads();
    for (int k = 2; k <= 512; k <<= 1) {
        for (int j = k >> 1; j > 0; j >>= 1) {
            int ixj = tid ^ j;
            if (ixj > tid) {
                unsigned long long a = key[tid], b = key[ixj];
                if (((tid & k) == 0) ? (a < b) : (a > b)) { key[tid] = b; key[ixj] = a; }
            }
            __syncthreads();
        }
    }
    if (tid < KOUT) {
        unsigned long long kk = key[tid];
        float s = __uint_as_float((unsigned)(kk >> 32));
        unsigned pos = 0xFFFFFFFFu - (unsigned)(kk & 0xFFFFFFFFull);
        int o = img * KCAND + (int)pos;
        int r = img * KOUT + tid;
        out[r * 4 + 0] = g_cbox[o * 4 + 0];
        out[r * 4 + 1] = g_cbox[o * 4 + 1];
        out[r * 4 + 2] = g_cbox[o * 4 + 2];
        out[r * 4 + 3] = g_cbox[o * 4 + 3];
        out[NIMG * KOUT * 4 + r] = s;
        out[NIMG * KOUT * 5 + r] = (s > 0.f) ? (float)g_ccls[o] : 0.f;
    }
}

extern "C" void kernel_launch(void* const* d_in, const int* in_sizes, int n_in,
                              void* d_out, int out_size)
{
    (void)out_size;
    int fi[6], cwi[6], cbi[6], rwi[6], rbi[6], pi = 30;
    bool grouped = (n_in > 1 && in_sizes[1] == 5914624);
    for (int i = 0; i < 6; i++) {
        if (grouped) {
            fi[i] = i;            cwi[i] = 6 + 2 * i;  cbi[i] = 7 + 2 * i;
            rwi[i] = 18 + 2 * i;  rbi[i] = 19 + 2 * i;
        } else {
            fi[i] = 5 * i;        cwi[i] = 5 * i + 1;  cbi[i] = 5 * i + 2;
            rwi[i] = 5 * i + 3;   rbi[i] = 5 * i + 4;
        }
    }

    static const int Cs[6]   = {512, 1024, 512, 256, 256, 256};
    static const int Hs[6]   = {38, 19, 10, 5, 3, 1};
    static const int ANs[6]  = {4, 6, 6, 6, 4, 4};
    static const int BASE[6] = {0, 5776, 7942, 8542, 8692, 8728};

    float *p_cls, *p_reg;
    cudaGetSymbolAddress((void**)&p_cls, g_cls);
    cudaGetSymbolAddress((void**)&p_reg, g_reg);

    // LPT schedule: longest per-CTA latency first.
    // slot ids: 0-5 cls head i, 6-11 reg head i-6
    static const int ord[12] = {1, 0, 2, 7, 6, 3, 4, 5, 8, 9, 10, 11};

    AllDesc D;
    int cum = 0;
    for (int sIdx = 0; sIdx < 12; sIdx++) {
        int hid = ord[sIdx];
        int i = (hid < 6) ? hid : hid - 6;
        int N = NIMG * Hs[i] * Hs[i];
        D.x[sIdx]  = (const float*)d_in[fi[i]];
        D.C[sIdx] = Cs[i]; D.H[sIdx] = Hs[i];
        D.base[sIdx] = BASE[i]; D.an[sIdx] = ANs[i];
        D.cta0[sIdx] = cum;
        if (hid < 6) {   // cls: 128x64 tiles
            D.w[sIdx]  = (const float*)d_in[cwi[i]];
            D.bs[sIdx] = (const float*)d_in[cbi[i]];
            D.OC[sIdx] = ANs[i] * NCLS1;
            D.tl[sIdx] = NCLS1;
            D.gx[sIdx] = (N + 63) / 64;
            cum += D.gx[sIdx] * ((D.OC[sIdx] + 127) / 128);
        } else {         // reg: 128 pixels per CTA
            D.w[sIdx]  = (const float*)d_in[rwi[i]];
            D.bs[sIdx] = (const float*)d_in[rbi[i]];
            D.OC[sIdx] = ANs[i] * 4;
            D.tl[sIdx] = 4;
            D.gx[sIdx] = (N + 127) / 128;
            cum += D.gx[sIdx];
        }
    }

    // launches 1-3: zero parts; launch 4: conv_all (target of the ncu window)
    for (int p = 0; p < 3; p++)
        zero_kernel<<<(ZPART + 255) / 256, 256>>>(p);
    conv_all<<<cum, 128>>>(D, p_cls, p_reg);

    softmax_kernel<<<(NIMG * NANCH + 7) / 8, 256>>>();
    int tot = NIMG * NANCH * NCLS;
    hist_kernel<<<(tot + 255) / 256, 256>>>();
    select_kernel<<<NIMG, 256>>>();
    compact_kernel<<<(tot + 255) / 256, 256>>>();
    cudaFuncSetAttribute(sort_decode_kernel, cudaFuncAttributeMaxDynamicSharedMemorySize, CAP * 8);
    sort_decode_kernel<<<NIMG, 1024, CAP * 8>>>((const float*)d_in[pi]);
    nms_kernel<<<NIMG, 256>>>();
    final_kernel<<<NIMG, 512>>>((float*)d_out);
}

// round 16
// speedup vs baseline: 1.0911x; 1.0911x over previous
#include <cuda_runtime.h>
#include <stdint.h>
#include <math.h>

#define NIMG   16
#define NANCH  8732
#define NCLS   80
#define NCLS1  81
#define KCAND  400
#define KOUT   200
#define CAP    16384
#define CLIPV  4.135166556742356f

__device__ float g_cls[NIMG * NANCH * NCLS1];
__device__ float g_reg[NIMG * NANCH * 4];
__device__ float g_scr[NIMG * NANCH * NCLS];
__device__ unsigned int g_hist[NIMG * 65536];
__device__ unsigned int g_thr[NIMG];
__device__ int g_cnt[NIMG];
__device__ unsigned long long g_cand[NIMG * CAP];
__device__ float g_cbox[NIMG * KCAND * 4];
__device__ float g_cscore[NIMG * KCAND];
__device__ int g_ccls[NIMG * KCAND];
__device__ int g_ckeep[NIMG * KCAND];

// f32x2 helpers
#define FMA2(acc, a, b) asm("fma.rn.f32x2 %0, %1, %2, %0;" : "+l"(acc) : "l"(a), "l"(b))
#define PACK2(out, lo, hi) asm("mov.b64 %0, {%1, %2};" : "=l"(out) : "r"(lo), "r"(hi))
#define UNPACK2(lo, hi, in) asm("mov.b64 {%0, %1}, %2;" : "=r"(lo), "=r"(hi) : "l"(in))

// zero hist in 3 parts so conv_all is visible launch #4 (ncu -s 5 window)
#define ZPART 349526
__global__ void zero_kernel(int part) {
    int i = part * ZPART + blockIdx.x * blockDim.x + threadIdx.x;
    if (i < NIMG * 65536 && i < (part + 1) * ZPART) g_hist[i] = 0u;
    if (part == 0 && blockIdx.x == 0 && threadIdx.x < NIMG) g_cnt[threadIdx.x] = 0;
}

// ---------------- one fused conv for all 12 heads (Round-11 best config) ----------------
struct AllDesc {
    const float* x[12];
    const float* w[12];
    const float* bs[12];
    int C[12], H[12], OC[12], base[12], an[12], cta0[12], gx[12], tl[12];
};

__global__ __launch_bounds__(256) void conv_all(AllDesc D, float* __restrict__ outc,
                                                float* __restrict__ outr)
{
    __shared__ float As[2][16][128];
    __shared__ float Bs[2][16][128];

    int bid = blockIdx.x, s = 0;
#pragma unroll
    for (int i = 1; i < 12; i++) if (bid >= D.cta0[i]) s = i;
    int local = bid - D.cta0[s];
    const int C = D.C[s], H = D.H[s], W = H, OC = D.OC[s], an = D.an[s], base = D.base[s];
    const float* x = D.x[s];
    const float* w = D.w[s];
    const float* bias = D.bs[s];
    const int HW = H * W, N = NIMG * HW, K = C * 9, NCH = K >> 4;
    const int tid = threadIdx.x;

    if (D.tl[s] == NCLS1) {
        // ======== cls path: 128x128 tile, 8x8 microtile, FFMA2, pipelined ========
        int gx = D.gx[s];
        int bx = local % gx, by = local / gx;
        const int m0 = by * 128, n0 = bx * 128;
        const int bn = tid & 127, bkb = (tid >> 7) * 8;
        const int n = n0 + bn;
        const bool nv = (n < N);
        int bimg = 0, py = 0, px = 0;
        if (nv) { bimg = n / HW; int rem = n - bimg * HW; py = rem / W; px = rem - py * W; }
        const float* xb = x + (size_t)bimg * C * HW;
        const int am = tid >> 1, akb = (tid & 1) * 8;
        const bool mv = (m0 + am) < OC;
        const float* wp = w + (size_t)(m0 + am) * K;
        const int tx = tid & 15, ty = tid >> 4;

        unsigned long long ch2[32];
        float ms[64], cp[64], pa[8], pb[8];
#pragma unroll
        for (int j = 0; j < 32; j++) ch2[j] = 0ULL;
#pragma unroll
        for (int j = 0; j < 64; j++) { ms[j] = 0.f; cp[j] = 0.f; }

        auto ldg = [&](int c) {
            int k0 = c << 4;
            if (mv) {
                float4 a0 = *(const float4*)(wp + k0 + akb);
                float4 a1 = *(const float4*)(wp + k0 + akb + 4);
                pa[0] = a0.x; pa[1] = a0.y; pa[2] = a0.z; pa[3] = a0.w;
                pa[4] = a1.x; pa[5] = a1.y; pa[6] = a1.z; pa[7] = a1.w;
            } else {
#pragma unroll
                for (int i = 0; i < 8; i++) pa[i] = 0.f;
            }
#pragma unroll
            for (int i = 0; i < 8; i++) {
                int k = k0 + bkb + i;
                int ic = k / 9, r = k - ic * 9, ky = r / 3, kx = r - ky * 3;
                int iy = py + ky - 1, ix = px + kx - 1;
                float v = 0.f;
                if (nv && (unsigned)iy < (unsigned)H && (unsigned)ix < (unsigned)W)
                    v = xb[(ic * H + iy) * W + ix];
                pb[i] = v;
            }
        };
        auto st = [&](int bb) {
#pragma unroll
            for (int i = 0; i < 8; i++) As[bb][akb + i][am] = pa[i];
#pragma unroll
            for (int i = 0; i < 8; i++) Bs[bb][bkb + i][bn] = pb[i];
        };

        ldg(0); st(0); __syncthreads();

        for (int c = 0; c < NCH; c++) {
            const int b = c & 1;
            if (c + 1 < NCH) ldg(c + 1);
#pragma unroll
            for (int kk = 0; kk < 16; kk++) {
                ulonglong2 Ap0 = *(const ulonglong2*)&As[b][kk][ty * 8];
                ulonglong2 Ap1 = *(const ulonglong2*)&As[b][kk][ty * 8 + 4];
                unsigned long long a2[4] = {Ap0.x, Ap0.y, Ap1.x, Ap1.y};
                float4 B0 = *(const float4*)&Bs[b][kk][tx * 8];
                float4 B1 = *(const float4*)&Bs[b][kk][tx * 8 + 4];
                float bv[8] = {B0.x, B0.y, B0.z, B0.w, B1.x, B1.y, B1.z, B1.w};
                unsigned long long b2[8];
#pragma unroll
                for (int j = 0; j < 8; j++) {
                    unsigned br = __float_as_uint(bv[j]);
                    PACK2(b2[j], br, br);
                }
#pragma unroll
                for (int i2 = 0; i2 < 4; i2++)
#pragma unroll
                    for (int j = 0; j < 8; j++)
                        FMA2(ch2[i2 * 8 + j], a2[i2], b2[j]);
            }
            if ((c & 3) == 3) {   // Kahan merge every 64 k (NCH % 4 == 0 for all heads)
#pragma unroll
                for (int i2 = 0; i2 < 4; i2++)
#pragma unroll
                    for (int j = 0; j < 8; j++) {
                        unsigned rlo, rhi;
                        UNPACK2(rlo, rhi, ch2[i2 * 8 + j]);
                        int e0 = (2 * i2) * 8 + j, e1 = (2 * i2 + 1) * 8 + j;
                        float v0 = __uint_as_float(rlo), v1 = __uint_as_float(rhi);
                        float y0 = __fsub_rn(v0, cp[e0]);
                        float t0 = __fadd_rn(ms[e0], y0);
                        cp[e0] = __fsub_rn(__fsub_rn(t0, ms[e0]), y0);
                        ms[e0] = t0;
                        float y1 = __fsub_rn(v1, cp[e1]);
                        float t1 = __fadd_rn(ms[e1], y1);
                        cp[e1] = __fsub_rn(__fsub_rn(t1, ms[e1]), y1);
                        ms[e1] = t1;
                        ch2[i2 * 8 + j] = 0ULL;
                    }
            }
            if (c + 1 < NCH) { st(b ^ 1); __syncthreads(); }
        }

#pragma unroll
        for (int i = 0; i < 8; i++) {
            int m = m0 + ty * 8 + i;
            if (m >= OC) continue;
            float bv = bias[m];
            int a_idx = m / NCLS1, t = m - a_idx * NCLS1;
#pragma unroll
            for (int j = 0; j < 8; j++) {
                int nn = n0 + tx * 8 + j;
                if (nn >= N) continue;
                int bi = nn / HW, rem = nn - bi * HW;
                int anchor = base + rem * an + a_idx;
                outc[((size_t)bi * NANCH + anchor) * NCLS1 + t] =
                    __fadd_rn(__fadd_rn(ms[i * 8 + j], cp[i * 8 + j]), bv);
            }
        }
    } else {
        // ======== reg path: 256 pixels/CTA, thread owns a column of 24 oc ========
        const int n = local * 256 + tid;
        const bool nv = (n < N);
        int bimg = 0, py = 0, px = 0;
        if (nv) { bimg = n / HW; int rem = n - bimg * HW; py = rem / W; px = rem - py * W; }
        const float* xb = x + (size_t)bimg * C * HW;
        float* Asr = &As[0][0][0];   // 16 x 24 chunk of weights

        float acc[24], cpp[24], chh[24];
#pragma unroll
        for (int m = 0; m < 24; m++) { acc[m] = 0.f; cpp[m] = 0.f; chh[m] = 0.f; }

        for (int c = 0; c < NCH; c++) {
            int k0 = c << 4;
            float bvv[16];
#pragma unroll
            for (int i = 0; i < 16; i++) {
                int k = k0 + i;
                int ic = k / 9, r = k - ic * 9, ky = r / 3, kx = r - ky * 3;
                int iy = py + ky - 1, ix = px + kx - 1;
                float v = 0.f;
                if (nv && (unsigned)iy < (unsigned)H && (unsigned)ix < (unsigned)W)
                    v = xb[(ic * H + iy) * W + ix];
                bvv[i] = v;
            }
            for (int f = tid; f < 384; f += 256) {
                int k = f / 24, m = f - k * 24;
                Asr[k * 24 + m] = (m < OC) ? w[(size_t)m * K + k0 + k] : 0.f;
            }
            __syncthreads();
#pragma unroll
            for (int kk = 0; kk < 16; kk++) {
                float b = bvv[kk];
#pragma unroll
                for (int m = 0; m < 24; m++)
                    chh[m] += Asr[kk * 24 + m] * b;
            }
            __syncthreads();
            if (c & 1) {
#pragma unroll
                for (int m = 0; m < 24; m++) {
                    float y = __fsub_rn(chh[m], cpp[m]);
                    float t = __fadd_rn(acc[m], y);
                    cpp[m] = __fsub_rn(__fsub_rn(t, acc[m]), y);
                    acc[m] = t;
                    chh[m] = 0.f;
                }
            }
        }
        if (nv) {
            int bi = n / HW, rem = n - bi * HW;
            for (int m = 0; m < OC; m++) {
                int a_idx = m >> 2, t = m & 3;
                int anchor = base + rem * an + a_idx;
                outr[((size_t)bi * NANCH + anchor) * 4 + t] =
                    __fadd_rn(__fadd_rn(acc[m], cpp[m]), bias[m]);
            }
        }
    }
}

__global__ void softmax_kernel() {
    int gw = (blockIdx.x * blockDim.x + threadIdx.x) >> 5;
    int lane = threadIdx.x & 31;
    if (gw >= NIMG * NANCH) return;
    const float* row = g_cls + (size_t)gw * NCLS1;
    float x0 = row[lane], x1 = row[lane + 32];
    float x2 = (lane < 17) ? row[lane + 64] : -3.4e38f;
    float m = fmaxf(x0, fmaxf(x1, x2));
    for (int o = 16; o; o >>= 1) m = fmaxf(m, __shfl_xor_sync(0xffffffffu, m, o));
    float e0 = expf(x0 - m), e1 = expf(x1 - m);
    float e2 = (lane < 17) ? expf(x2 - m) : 0.f;
    float s = e0 + e1 + e2;
    for (int o = 16; o; o >>= 1) s += __shfl_xor_sync(0xffffffffu, s, o);
    float* outp = g_scr + (size_t)gw * NCLS;
    if (lane >= 1) { float p = e0 / s; outp[lane - 1]  = (p > 0.01f) ? p : 0.f; }
    {               float p = e1 / s; outp[lane + 31] = (p > 0.01f) ? p : 0.f; }
    if (lane < 17) { float p = e2 / s; outp[lane + 63] = (p > 0.01f) ? p : 0.f; }
}

__global__ void hist_kernel() {
    int i = blockIdx.x * blockDim.x + threadIdx.x;
    if (i >= NIMG * NANCH * NCLS) return;
    unsigned b = __float_as_uint(g_scr[i]);
    if (b) {
        int img = i / (NANCH * NCLS);
        atomicAdd(&g_hist[img * 65536 + (b >> 16)], 1u);
    }
}

__global__ void select_kernel() {
    __shared__ unsigned csum[256];
    int img = blockIdx.x, tid = threadIdx.x;
    const unsigned* h = g_hist + img * 65536;
    unsigned s = 0;
    for (int j = 0; j < 256; j++) s += h[tid * 256 + j];
    csum[tid] = s;
    __syncthreads();
    if (tid == 0) {
        unsigned cum = 0; int c;
        for (c = 255; c >= 0; c--) {
            if (cum + csum[c] >= KCAND) break;
            cum += csum[c];
        }
        unsigned T = 1u;
        if (c >= 0) {
            int b;
            for (b = c * 256 + 255; b >= c * 256; b--) {
                cum += h[b];
                if (cum >= KCAND) break;
            }
            if (b < c * 256) b = c * 256;
            T = ((unsigned)b) << 16;
            if (T == 0u) T = 1u;
        }
        g_thr[img] = T;
    }
}

__global__ void compact_kernel() {
    int i = blockIdx.x * blockDim.x + threadIdx.x;
    if (i >= NIMG * NANCH * NCLS) return;
    unsigned b = __float_as_uint(g_scr[i]);
    int img = i / (NANCH * NCLS);
    if (b >= g_thr[img]) {
        int p = atomicAdd(&g_cnt[img], 1);
        if (p < CAP) {
            unsigned fidx = (unsigned)(i - img * NANCH * NCLS);
            g_cand[img * CAP + p] =
                ((unsigned long long)b << 32) | (unsigned long long)(0xFFFFFFFFu - fidx);
        }
    }
}

// ---------------- sort candidates: DYNAMIC bitonic length ----------------
__global__ void sort_decode_kernel(const float* __restrict__ priors) {
    extern __shared__ unsigned long long sk[];
    int img = blockIdx.x, tid = threadIdx.x, nt = blockDim.x;
    int cnt = g_cnt[img];
    if (cnt > CAP) cnt = CAP;
    // L = smallest pow2 >= max(cnt, 512), capped at CAP
    int L = 512;
    while (L < cnt) L <<= 1;
    if (L > CAP) L = CAP;
    for (int i = tid; i < L; i += nt)
        sk[i] = (i < cnt) ? g_cand[img * CAP + i] : 0ULL;
    __syncthreads();

    for (int k = 2; k <= L; k <<= 1) {
        for (int j = k >> 1; j > 0; j >>= 1) {
            for (int i = tid; i < L; i += nt) {
                int ixj = i ^ j;
                if (ixj > i) {
                    unsigned long long a = sk[i], b = sk[ixj];
                    bool desc = ((i & k) == 0);
                    if (desc ? (a < b) : (a > b)) { sk[i] = b; sk[ixj] = a; }
                }
            }
            __syncthreads();
        }
    }
    for (int r = tid; r < KCAND; r += nt) {
        unsigned long long key = sk[r];
        unsigned bits = (unsigned)(key >> 32);
        unsigned fidx = 0xFFFFFFFFu - (unsigned)(key & 0xFFFFFFFFull);
        float s = __uint_as_float(bits);
        if (bits == 0u) { s = 0.f; fidx = 0u; }
        int anc = (int)(fidx / NCLS);
        int cls = (int)(fidx - (unsigned)anc * NCLS) + 1;
        const float* d  = g_reg + ((size_t)img * NANCH + anc) * 4;
        const float* pr = priors + (size_t)anc * 4;
        float cx = __fadd_rn(pr[0], __fmul_rn(__fmul_rn(d[0], 0.1f), pr[2]));
        float cy = __fadd_rn(pr[1], __fmul_rn(__fmul_rn(d[1], 0.1f), pr[3]));
        float w  = __fmul_rn(pr[2], expf(fminf(__fmul_rn(d[2], 0.2f), CLIPV)));
        float h  = __fmul_rn(pr[3], expf(fminf(__fmul_rn(d[3], 0.2f), CLIPV)));
        float hw = __fmul_rn(0.5f, w), hh = __fmul_rn(0.5f, h);
        float x1 = fminf(fmaxf(__fsub_rn(cx, hw), 0.f), 300.f);
        float y1 = fminf(fmaxf(__fsub_rn(cy, hh), 0.f), 300.f);
        float x2 = fminf(fmaxf(__fadd_rn(cx, hw), 0.f), 300.f);
        float y2 = fminf(fmaxf(__fadd_rn(cy, hh), 0.f), 300.f);
        bool valid = (s > 0.f) && (x2 > x1) && (y2 > y1);
        int o = img * KCAND + r;
        g_cbox[o * 4 + 0] = x1; g_cbox[o * 4 + 1] = y1;
        g_cbox[o * 4 + 2] = x2; g_cbox[o * 4 + 3] = y2;
        g_cscore[o] = valid ? s : 0.f;
        g_ccls[o] = cls;
        g_ckeep[o] = valid ? 1 : 0;
    }
}

__global__ void nms_kernel() {
    __shared__ float bx1[KCAND], by1[KCAND], bx2[KCAND], by2[KCAND], ar[KCAND];
    __shared__ int kc[KCAND], kp[KCAND];
    int img = blockIdx.x, tid = threadIdx.x, nt = blockDim.x;
    for (int i = tid; i < KCAND; i += nt) {
        int o = img * KCAND + i;
        int c = g_ccls[o];
        float off = __fmul_rn((float)c, 301.0f);
        float a1 = __fadd_rn(g_cbox[o * 4 + 0], off);
        float a2 = __fadd_rn(g_cbox[o * 4 + 1], off);
        float a3 = __fadd_rn(g_cbox[o * 4 + 2], off);
        float a4 = __fadd_rn(g_cbox[o * 4 + 3], off);
        bx1[i] = a1; by1[i] = a2; bx2[i] = a3; by2[i] = a4;
        ar[i] = __fmul_rn(__fsub_rn(a3, a1), __fsub_rn(a4, a2));
        kc[i] = c;
        kp[i] = g_ckeep[o];
    }
    for (int i = 0; i < KCAND; i++) {
        __syncthreads();
        if (!kp[i]) continue;
        float ix1 = bx1[i], iy1 = by1[i], ix2 = bx2[i], iy2 = by2[i], ia = ar[i];
        int ic = kc[i];
        for (int j = i + 1 + tid; j < KCAND; j += nt) {
            if (kp[j] && kc[j] == ic) {
                float w = fmaxf(__fsub_rn(fminf(ix2, bx2[j]), fmaxf(ix1, bx1[j])), 0.f);
                float h = fmaxf(__fsub_rn(fminf(iy2, by2[j]), fmaxf(iy1, by1[j])), 0.f);
                float inter = __fmul_rn(w, h);
                float denom = __fadd_rn(__fsub_rn(__fadd_rn(ia, ar[j]), inter), 1e-9f);
                if (__fdiv_rn(inter, denom) > 0.45f) kp[j] = 0;
            }
        }
    }
    __syncthreads();
    for (int i = tid; i < KCAND; i += nt) g_ckeep[img * KCAND + i] = kp[i];
}

__global__ void final_kernel(float* __restrict__ out) {
    __shared__ unsigned long long key[512];
    int img = blockIdx.x, tid = threadIdx.x;
    if (tid < KCAND) {
        int o = img * KCAND + tid;
        float ms = g_ckeep[o] ? g_cscore[o] : 0.f;
        key[tid] = ((unsigned long long)__float_as_uint(ms) << 32) |
                   (unsigned long long)(0xFFFFFFFFu - (unsigned)tid);
    } else key[tid] = 0ULL;
    __syncthreads();
    for (int k = 2; k <= 512; k <<= 1) {
        for (int j = k >> 1; j > 0; j >>= 1) {
            int ixj = tid ^ j;
            if (ixj > tid) {
                unsigned long long a = key[tid], b = key[ixj];
                if (((tid & k) == 0) ? (a < b) : (a > b)) { key[tid] = b; key[ixj] = a; }
            }
            __syncthreads();
        }
    }
    if (tid < KOUT) {
        unsigned long long kk = key[tid];
        float s = __uint_as_float((unsigned)(kk >> 32));
        unsigned pos = 0xFFFFFFFFu - (unsigned)(kk & 0xFFFFFFFFull);
        int o = img * KCAND + (int)pos;
        int r = img * KOUT + tid;
        out[r * 4 + 0] = g_cbox[o * 4 + 0];
        out[r * 4 + 1] = g_cbox[o * 4 + 1];
        out[r * 4 + 2] = g_cbox[o * 4 + 2];
        out[r * 4 + 3] = g_cbox[o * 4 + 3];
        out[NIMG * KOUT * 4 + r] = s;
        out[NIMG * KOUT * 5 + r] = (s > 0.f) ? (float)g_ccls[o] : 0.f;
    }
}

extern "C" void kernel_launch(void* const* d_in, const int* in_sizes, int n_in,
                              void* d_out, int out_size)
{
    (void)out_size;
    int fi[6], cwi[6], cbi[6], rwi[6], rbi[6], pi = 30;
    bool grouped = (n_in > 1 && in_sizes[1] == 5914624);
    for (int i = 0; i < 6; i++) {
        if (grouped) {
            fi[i] = i;            cwi[i] = 6 + 2 * i;  cbi[i] = 7 + 2 * i;
            rwi[i] = 18 + 2 * i;  rbi[i] = 19 + 2 * i;
        } else {
            fi[i] = 5 * i;        cwi[i] = 5 * i + 1;  cbi[i] = 5 * i + 2;
            rwi[i] = 5 * i + 3;   rbi[i] = 5 * i + 4;
        }
    }

    static const int Cs[6]   = {512, 1024, 512, 256, 256, 256};
    static const int Hs[6]   = {38, 19, 10, 5, 3, 1};
    static const int ANs[6]  = {4, 6, 6, 6, 4, 4};
    static const int BASE[6] = {0, 5776, 7942, 8542, 8692, 8728};

    float *p_cls, *p_reg;
    cudaGetSymbolAddress((void**)&p_cls, g_cls);
    cudaGetSymbolAddress((void**)&p_reg, g_reg);

    // LPT schedule: longest per-CTA latency first.
    static const int ord[12] = {1, 0, 2, 7, 6, 3, 4, 5, 8, 9, 10, 11};

    AllDesc D;
    int cum = 0;
    for (int sIdx = 0; sIdx < 12; sIdx++) {
        int hid = ord[sIdx];
        int i = (hid < 6) ? hid : hid - 6;
        int N = NIMG * Hs[i] * Hs[i];
        D.x[sIdx]  = (const float*)d_in[fi[i]];
        D.C[sIdx] = Cs[i]; D.H[sIdx] = Hs[i];
        D.base[sIdx] = BASE[i]; D.an[sIdx] = ANs[i];
        D.cta0[sIdx] = cum;
        if (hid < 6) {   // cls: 128x128 tiles
            D.w[sIdx]  = (const float*)d_in[cwi[i]];
            D.bs[sIdx] = (const float*)d_in[cbi[i]];
            D.OC[sIdx] = ANs[i] * NCLS1;
            D.tl[sIdx] = NCLS1;
            D.gx[sIdx] = (N + 127) / 128;
            cum += D.gx[sIdx] * ((D.OC[sIdx] + 127) / 128);
        } else {         // reg: 256 pixels per CTA
            D.w[sIdx]  = (const float*)d_in[rwi[i]];
            D.bs[sIdx] = (const float*)d_in[rbi[i]];
            D.OC[sIdx] = ANs[i] * 4;
            D.tl[sIdx] = 4;
            D.gx[sIdx] = (N + 255) / 256;
            cum += D.gx[sIdx];
        }
    }

    // launches 1-3: zero parts; launch 4: conv_all (ncu window target)
    for (int p = 0; p < 3; p++)
        zero_kernel<<<(ZPART + 255) / 256, 256>>>(p);
    conv_all<<<cum, 256>>>(D, p_cls, p_reg);

    softmax_kernel<<<(NIMG * NANCH + 7) / 8, 256>>>();
    int tot = NIMG * NANCH * NCLS;
    hist_kernel<<<(tot + 255) / 256, 256>>>();
    select_kernel<<<NIMG, 256>>>();
    compact_kernel<<<(tot + 255) / 256, 256>>>();
    cudaFuncSetAttribute(sort_decode_kernel, cudaFuncAttributeMaxDynamicSharedMemorySize, CAP * 8);
    sort_decode_kernel<<<NIMG, 1024, CAP * 8>>>((const float*)d_in[pi]);
    nms_kernel<<<NIMG, 256>>>();
    final_kernel<<<NIMG, 512>>>((float*)d_out);
}